// round 12
// baseline (speedup 1.0000x reference)
#include <cuda_runtime.h>

// Bilinear 2x upsample, half_pixel_centers=False (asymmetric: h = hd/2).
// Input : (16, 64, 128, 128) fp32, Output: (16, 64, 256, 256) fp32.
//
// R12 = R11 resubmitted verbatim (R11 bench was an infra failure — container
// died twice; kernel never ran). 4 input rows per warp: last point on the
// tile-size axis. Established across R5-R10: ~5.5TB/s pure-write HBM wall
// (DRAM=67.5%, path/policy/occupancy-independent). This variant reads each
// input row 1.25x (5 row-loads / 4 rows) vs 1.5x and cuts shfl+index
// overhead per output byte ~20%, probing the 3% gap to the 48.8us floor.
//
// Stencil (exact, neighbors clamped at 127):
//   out[2i  ][2j  ] = x[i][j]
//   out[2i  ][2j+1] = (x[i][j] + x[i][j+1]) / 2
//   odd output rows = average of adjacent even-row expansions (H is linear)
//
// Warp r handles input rows 4r..4r+3 (loads 4r..4r+4, last clamped) and
// emits output rows 8r..8r+7. All loads are 256B coalesced float2 warp
// transactions; all 16 stores are 512B coalesced float4 warp transactions.

static constexpr int SRC_H = 128;
static constexpr int SRC_W = 128;
static constexpr int NC    = 16 * 64;   // 1024
static constexpr int DST_W = 256;

struct RowData {
    float2 v0, v1;   // cols (2l, 2l+1) and (64+2l, 64+2l+1)
    float  n0, n1;   // right neighbors: cols 2l+2 and 64+2l+2 (clamped)
};

__device__ __forceinline__ void load_row(RowData& R, const float* img, int row, int lane) {
    const float2* p = reinterpret_cast<const float2*>(img + row * SRC_W);
    R.v0 = __ldg(p + lane);
    R.v1 = __ldg(p + 32 + lane);
}

__device__ __forceinline__ void resolve_neighbors(RowData& R, int lane, int nxt) {
    const unsigned F = 0xffffffffu;
    float s0 = __shfl_sync(F, R.v0.x, nxt);   // lane+1's first-half leading elem
    float s1 = __shfl_sync(F, R.v1.x, nxt);   // lane+1's second-half leading elem
    float t  = __shfl_sync(F, R.v1.x, 0);     // col 64 (for lane 31, half 0)
    R.n0 = (lane == 31) ? t : s0;
    R.n1 = (lane == 31) ? R.v1.y : s1;        // col 128 clamps to 127
}

__device__ __forceinline__ void h_expand(const RowData& r, float4& e0, float4& e1) {
    e0 = make_float4(r.v0.x, 0.5f * (r.v0.x + r.v0.y),
                     r.v0.y, 0.5f * (r.v0.y + r.n0));
    e1 = make_float4(r.v1.x, 0.5f * (r.v1.x + r.v1.y),
                     r.v1.y, 0.5f * (r.v1.y + r.n1));
}

__device__ __forceinline__ float4 avg4(const float4& a, const float4& b) {
    return make_float4(0.5f * (a.x + b.x), 0.5f * (a.y + b.y),
                       0.5f * (a.z + b.z), 0.5f * (a.w + b.w));
}

__global__ void __launch_bounds__(256)
bilinear2x_kernel(const float* __restrict__ in, float* __restrict__ out) {
    const int warp_global = blockIdx.x * (blockDim.x >> 5) + (threadIdx.x >> 5);
    const int lane = threadIdx.x & 31;
    const int nxt  = (lane + 1) & 31;

    const int nc = warp_global >> 5;        // / 32 row-quads per image
    const int r  = warp_global & 31;        // row-quad index
    const int i0 = 4 * r;

    const float* img = in + (size_t)nc * (SRC_H * SRC_W);

    // Front-batch all 10 independent coalesced loads (rows i0..i0+4, last clamped)
    RowData A, B, C, D, E;
    const int iE = (i0 + 4 < SRC_H) ? (i0 + 4) : (SRC_H - 1);
    load_row(A, img, i0,     lane);
    load_row(B, img, i0 + 1, lane);
    load_row(C, img, i0 + 2, lane);
    load_row(D, img, i0 + 3, lane);
    load_row(E, img, iE,     lane);

    resolve_neighbors(A, lane, nxt);
    resolve_neighbors(B, lane, nxt);
    resolve_neighbors(C, lane, nxt);
    resolve_neighbors(D, lane, nxt);
    resolve_neighbors(E, lane, nxt);

    float4 hA0, hA1, hB0, hB1, hC0, hC1, hD0, hD1, hE0, hE1;
    h_expand(A, hA0, hA1);
    h_expand(B, hB0, hB1);
    h_expand(C, hC0, hC1);
    h_expand(D, hD0, hD1);
    h_expand(E, hE0, hE1);

    float* outImg = out + (size_t)nc * (2 * SRC_H * DST_W);
    float4* obase = reinterpret_cast<float4*>(outImg + (8 * r) * DST_W);
    const int R4 = DST_W / 4;   // float4 per output row

    // 16 fully-coalesced 512B warp stores; streaming (output never re-read)
    __stcs(obase + 0 * R4 + lane,      hA0);
    __stcs(obase + 0 * R4 + 32 + lane, hA1);
    __stcs(obase + 1 * R4 + lane,      avg4(hA0, hB0));
    __stcs(obase + 1 * R4 + 32 + lane, avg4(hA1, hB1));
    __stcs(obase + 2 * R4 + lane,      hB0);
    __stcs(obase + 2 * R4 + 32 + lane, hB1);
    __stcs(obase + 3 * R4 + lane,      avg4(hB0, hC0));
    __stcs(obase + 3 * R4 + 32 + lane, avg4(hB1, hC1));
    __stcs(obase + 4 * R4 + lane,      hC0);
    __stcs(obase + 4 * R4 + 32 + lane, hC1);
    __stcs(obase + 5 * R4 + lane,      avg4(hC0, hD0));
    __stcs(obase + 5 * R4 + 32 + lane, avg4(hC1, hD1));
    __stcs(obase + 6 * R4 + lane,      hD0);
    __stcs(obase + 6 * R4 + 32 + lane, hD1);
    __stcs(obase + 7 * R4 + lane,      avg4(hD0, hE0));
    __stcs(obase + 7 * R4 + 32 + lane, avg4(hD1, hE1));
}

extern "C" void kernel_launch(void* const* d_in, const int* in_sizes, int n_in,
                              void* d_out, int out_size) {
    const float* x = (const float*)d_in[0];
    float* out = (float*)d_out;

    const int total_warps = NC * (SRC_H / 4);         // 32768 row-quads
    const int threads = 256;                          // 8 warps/block
    const int blocks = total_warps / (threads / 32);  // 4096

    bilinear2x_kernel<<<blocks, threads>>>(x, out);
}

// round 14
// speedup vs baseline: 1.0388x; 1.0388x over previous
#include <cuda_runtime.h>

// Bilinear 2x upsample, half_pixel_centers=False (asymmetric: h = hd/2).
// Input : (16, 64, 128, 128) fp32, Output: (16, 64, 256, 256) fp32.
//
// FINAL KERNEL (= R6, the measured optimum; R13 bench was an infra failure —
// container died twice, kernel never ran — so this is a verbatim resubmit).
// Evidence R5-R12:
//  - store path (STG / __stcs / __stwt / 32KB cp.async.bulk): identical perf
//  - tile size (1 / 2 / 4 rows per warp): 50.5 / 50.2 / 52.0 us kernel
//  - occupancy 55-79%: no effect
// => ~5.5TB/s pure-write HBM wall; this kernel is within ~3% of the
// 268.4MB compulsory-write traffic floor (48.8us). rel_err = 0.0.
//
// Stencil (exact, neighbors clamped at 127):
//   out[2i  ][2j  ] = x[i][j]
//   out[2i  ][2j+1] = (x[i][j] + x[i][j+1]) / 2
//   odd output rows = average of adjacent even-row expansions (H is linear)
//
// One warp per input ROW PAIR (2r, 2r+1): loads rows 2r, 2r+1, 2r+2 (clamped)
// via 6 coalesced 256B float2 warp loads, emits output rows 4r..4r+3 via 8
// fully-coalesced 512B float4 warp stores (each = 4 exact cache lines).

static constexpr int SRC_H = 128;
static constexpr int SRC_W = 128;
static constexpr int NC    = 16 * 64;   // 1024
static constexpr int DST_W = 256;

struct RowData {
    float2 v0, v1;   // cols (2l, 2l+1) and (64+2l, 64+2l+1)
    float  n0, n1;   // right neighbors: cols 2l+2 and 64+2l+2 (clamped)
};

__device__ __forceinline__ void h_expand(const RowData& r, float4& e0, float4& e1) {
    e0 = make_float4(r.v0.x, 0.5f * (r.v0.x + r.v0.y),
                     r.v0.y, 0.5f * (r.v0.y + r.n0));
    e1 = make_float4(r.v1.x, 0.5f * (r.v1.x + r.v1.y),
                     r.v1.y, 0.5f * (r.v1.y + r.n1));
}

__device__ __forceinline__ float4 avg4(const float4& a, const float4& b) {
    return make_float4(0.5f * (a.x + b.x), 0.5f * (a.y + b.y),
                       0.5f * (a.z + b.z), 0.5f * (a.w + b.w));
}

__global__ void __launch_bounds__(256)
bilinear2x_kernel(const float* __restrict__ in, float* __restrict__ out) {
    const unsigned F = 0xffffffffu;
    const int warp_global = blockIdx.x * (blockDim.x >> 5) + (threadIdx.x >> 5);
    const int lane = threadIdx.x & 31;

    const int nc = warp_global >> 6;        // / 64 row-pairs per image
    const int r  = warp_global & 63;        // row-pair index
    const int iA = 2 * r;
    const int iB = 2 * r + 1;
    const int iC = (iB < SRC_H - 1) ? (iB + 1) : iB;   // clamp bottom

    const float* img = in + (size_t)nc * (SRC_H * SRC_W);
    const float2* rowA = reinterpret_cast<const float2*>(img + iA * SRC_W);
    const float2* rowB = reinterpret_cast<const float2*>(img + iB * SRC_W);
    const float2* rowC = reinterpret_cast<const float2*>(img + iC * SRC_W);

    // Front-batch all 6 independent coalesced loads (256B warp transactions)
    RowData A, B, C;
    A.v0 = __ldg(rowA + lane);      A.v1 = __ldg(rowA + 32 + lane);
    B.v0 = __ldg(rowB + lane);      B.v1 = __ldg(rowB + 32 + lane);
    C.v0 = __ldg(rowC + lane);      C.v1 = __ldg(rowC + 32 + lane);

    const int nxt = (lane + 1) & 31;

    // Right-neighbor resolution per row:
    //   half 0: lanes 0..30 -> lane+1's v0.x ; lane 31 -> col 64 = lane 0's v1.x
    //   half 1: lanes 0..30 -> lane+1's v1.x ; lane 31 -> clamp to own v1.y
    {
        float s0 = __shfl_sync(F, A.v0.x, nxt);
        float s1 = __shfl_sync(F, A.v1.x, nxt);
        float t  = __shfl_sync(F, A.v1.x, 0);
        A.n0 = (lane == 31) ? t : s0;
        A.n1 = (lane == 31) ? A.v1.y : s1;
    }
    {
        float s0 = __shfl_sync(F, B.v0.x, nxt);
        float s1 = __shfl_sync(F, B.v1.x, nxt);
        float t  = __shfl_sync(F, B.v1.x, 0);
        B.n0 = (lane == 31) ? t : s0;
        B.n1 = (lane == 31) ? B.v1.y : s1;
    }
    {
        float s0 = __shfl_sync(F, C.v0.x, nxt);
        float s1 = __shfl_sync(F, C.v1.x, nxt);
        float t  = __shfl_sync(F, C.v1.x, 0);
        C.n0 = (lane == 31) ? t : s0;
        C.n1 = (lane == 31) ? C.v1.y : s1;
    }

    // Horizontal expansions of the three input rows
    float4 eA0, eA1, eB0, eB1, eC0, eC1;
    h_expand(A, eA0, eA1);
    h_expand(B, eB0, eB1);
    h_expand(C, eC0, eC1);

    float* outImg = out + (size_t)nc * (2 * SRC_H * DST_W);
    float4* o0 = reinterpret_cast<float4*>(outImg + (4 * r + 0) * DST_W);
    float4* o1 = reinterpret_cast<float4*>(outImg + (4 * r + 1) * DST_W);
    float4* o2 = reinterpret_cast<float4*>(outImg + (4 * r + 2) * DST_W);
    float4* o3 = reinterpret_cast<float4*>(outImg + (4 * r + 3) * DST_W);

    // 8 fully-coalesced 512B warp stores; streaming hint (output never re-read)
    __stcs(o0 + lane,      eA0);
    __stcs(o0 + 32 + lane, eA1);
    __stcs(o1 + lane,      avg4(eA0, eB0));
    __stcs(o1 + 32 + lane, avg4(eA1, eB1));
    __stcs(o2 + lane,      eB0);
    __stcs(o2 + 32 + lane, eB1);
    __stcs(o3 + lane,      avg4(eB0, eC0));
    __stcs(o3 + 32 + lane, avg4(eB1, eC1));
}

extern "C" void kernel_launch(void* const* d_in, const int* in_sizes, int n_in,
                              void* d_out, int out_size) {
    const float* x = (const float*)d_in[0];
    float* out = (float*)d_out;

    const int total_warps = NC * (SRC_H / 2);         // 65536 row-pairs
    const int threads = 256;                          // 8 warps/block
    const int blocks = total_warps / (threads / 32);  // 8192

    bilinear2x_kernel<<<blocks, threads>>>(x, out);
}

// round 15
// speedup vs baseline: 1.0394x; 1.0006x over previous
#include <cuda_runtime.h>

// Bilinear 2x upsample, half_pixel_centers=False (asymmetric: h = hd/2).
// Input : (16, 64, 128, 128) fp32, Output: (16, 64, 256, 256) fp32.
//
// FINAL KERNEL — measured optimum, reproduced 3x (55.296/55.456/55.328 us
// bench; ~50.2-50.7 us kernel; rel_err 0.0). Evidence R5-R14:
//  - store path (STG / __stcs / __stwt / 32KB cp.async.bulk): identical perf
//  - tile size (1 / 2 / 4 rows per warp): 50.5 / 50.2 / 52.0 us kernel
//  - occupancy 55-79%: no effect
// => path/policy/occupancy-independent ~5.5TB/s pure-write HBM wall;
// within ~3% of the 268.4MB compulsory-write traffic floor (48.8us).
//
// Stencil (exact, neighbors clamped at 127):
//   out[2i  ][2j  ] = x[i][j]
//   out[2i  ][2j+1] = (x[i][j] + x[i][j+1]) / 2
//   odd output rows = average of adjacent even-row expansions (H is linear)
//
// One warp per input ROW PAIR (2r, 2r+1): loads rows 2r, 2r+1, 2r+2 (clamped)
// via 6 coalesced 256B float2 warp loads, emits output rows 4r..4r+3 via 8
// fully-coalesced 512B float4 warp stores (each = 4 exact cache lines).

static constexpr int SRC_H = 128;
static constexpr int SRC_W = 128;
static constexpr int NC    = 16 * 64;   // 1024
static constexpr int DST_W = 256;

struct RowData {
    float2 v0, v1;   // cols (2l, 2l+1) and (64+2l, 64+2l+1)
    float  n0, n1;   // right neighbors: cols 2l+2 and 64+2l+2 (clamped)
};

__device__ __forceinline__ void h_expand(const RowData& r, float4& e0, float4& e1) {
    e0 = make_float4(r.v0.x, 0.5f * (r.v0.x + r.v0.y),
                     r.v0.y, 0.5f * (r.v0.y + r.n0));
    e1 = make_float4(r.v1.x, 0.5f * (r.v1.x + r.v1.y),
                     r.v1.y, 0.5f * (r.v1.y + r.n1));
}

__device__ __forceinline__ float4 avg4(const float4& a, const float4& b) {
    return make_float4(0.5f * (a.x + b.x), 0.5f * (a.y + b.y),
                       0.5f * (a.z + b.z), 0.5f * (a.w + b.w));
}

__global__ void __launch_bounds__(256)
bilinear2x_kernel(const float* __restrict__ in, float* __restrict__ out) {
    const unsigned F = 0xffffffffu;
    const int warp_global = blockIdx.x * (blockDim.x >> 5) + (threadIdx.x >> 5);
    const int lane = threadIdx.x & 31;

    const int nc = warp_global >> 6;        // / 64 row-pairs per image
    const int r  = warp_global & 63;        // row-pair index
    const int iA = 2 * r;
    const int iB = 2 * r + 1;
    const int iC = (iB < SRC_H - 1) ? (iB + 1) : iB;   // clamp bottom

    const float* img = in + (size_t)nc * (SRC_H * SRC_W);
    const float2* rowA = reinterpret_cast<const float2*>(img + iA * SRC_W);
    const float2* rowB = reinterpret_cast<const float2*>(img + iB * SRC_W);
    const float2* rowC = reinterpret_cast<const float2*>(img + iC * SRC_W);

    // Front-batch all 6 independent coalesced loads (256B warp transactions)
    RowData A, B, C;
    A.v0 = __ldg(rowA + lane);      A.v1 = __ldg(rowA + 32 + lane);
    B.v0 = __ldg(rowB + lane);      B.v1 = __ldg(rowB + 32 + lane);
    C.v0 = __ldg(rowC + lane);      C.v1 = __ldg(rowC + 32 + lane);

    const int nxt = (lane + 1) & 31;

    // Right-neighbor resolution per row:
    //   half 0: lanes 0..30 -> lane+1's v0.x ; lane 31 -> col 64 = lane 0's v1.x
    //   half 1: lanes 0..30 -> lane+1's v1.x ; lane 31 -> clamp to own v1.y
    {
        float s0 = __shfl_sync(F, A.v0.x, nxt);
        float s1 = __shfl_sync(F, A.v1.x, nxt);
        float t  = __shfl_sync(F, A.v1.x, 0);
        A.n0 = (lane == 31) ? t : s0;
        A.n1 = (lane == 31) ? A.v1.y : s1;
    }
    {
        float s0 = __shfl_sync(F, B.v0.x, nxt);
        float s1 = __shfl_sync(F, B.v1.x, nxt);
        float t  = __shfl_sync(F, B.v1.x, 0);
        B.n0 = (lane == 31) ? t : s0;
        B.n1 = (lane == 31) ? B.v1.y : s1;
    }
    {
        float s0 = __shfl_sync(F, C.v0.x, nxt);
        float s1 = __shfl_sync(F, C.v1.x, nxt);
        float t  = __shfl_sync(F, C.v1.x, 0);
        C.n0 = (lane == 31) ? t : s0;
        C.n1 = (lane == 31) ? C.v1.y : s1;
    }

    // Horizontal expansions of the three input rows
    float4 eA0, eA1, eB0, eB1, eC0, eC1;
    h_expand(A, eA0, eA1);
    h_expand(B, eB0, eB1);
    h_expand(C, eC0, eC1);

    float* outImg = out + (size_t)nc * (2 * SRC_H * DST_W);
    float4* o0 = reinterpret_cast<float4*>(outImg + (4 * r + 0) * DST_W);
    float4* o1 = reinterpret_cast<float4*>(outImg + (4 * r + 1) * DST_W);
    float4* o2 = reinterpret_cast<float4*>(outImg + (4 * r + 2) * DST_W);
    float4* o3 = reinterpret_cast<float4*>(outImg + (4 * r + 3) * DST_W);

    // 8 fully-coalesced 512B warp stores; streaming hint (output never re-read)
    __stcs(o0 + lane,      eA0);
    __stcs(o0 + 32 + lane, eA1);
    __stcs(o1 + lane,      avg4(eA0, eB0));
    __stcs(o1 + 32 + lane, avg4(eA1, eB1));
    __stcs(o2 + lane,      eB0);
    __stcs(o2 + 32 + lane, eB1);
    __stcs(o3 + lane,      avg4(eB0, eC0));
    __stcs(o3 + 32 + lane, avg4(eB1, eC1));
}

extern "C" void kernel_launch(void* const* d_in, const int* in_sizes, int n_in,
                              void* d_out, int out_size) {
    const float* x = (const float*)d_in[0];
    float* out = (float*)d_out;

    const int total_warps = NC * (SRC_H / 2);         // 65536 row-pairs
    const int threads = 256;                          // 8 warps/block
    const int blocks = total_warps / (threads / 32);  // 8192

    bilinear2x_kernel<<<blocks, threads>>>(x, out);
}